// round 7
// baseline (speedup 1.0000x reference)
#include <cuda_runtime.h>
#include <math.h>

#define NB 16
#define NW 64
#define NIMG 1024
#define NPIX 4096
#define NYH 33
#define NMODE 2112
#define TSTEPS 20
typedef unsigned long long ull;

// ---------------- device global scratch ----------------
__device__ float  g_h [NIMG*NPIX];              // hidden state [b][w][x][y]
__device__ float  g_z [NIMG*NPIX];              // sigmoid(z)
__device__ float2 g_hf[(size_t)NIMG*NMODE];     // spectrum [img][mode]
__device__ float2 g_zf[(size_t)NIMG*NMODE];
__device__ float2 g_rf[(size_t)NIMG*NMODE];     // r-spec, then n-spec
__device__ float2 g_Wt[3][(size_t)NMODE*4096];  // weights [gate][mode][i*64+o]
__device__ float2 g_tw[64];                     // W64^k forward twiddles

// ---------------- helpers ----------------
__device__ __forceinline__ ull pack2(float x, float y){
  ull r; asm("mov.b64 %0,{%1,%2};":"=l"(r):"f"(x),"f"(y)); return r;
}
__device__ __forceinline__ void unpack2(ull v, float& x, float& y){
  asm("mov.b64 {%0,%1},%2;":"=f"(x),"=f"(y):"l"(v));
}
__device__ __forceinline__ ull ffma2(ull a, ull b, ull c){
  ull d; asm("fma.rn.f32x2 %0,%1,%2,%3;":"=l"(d):"l"(a),"l"(b),"l"(c)); return d;
}
__device__ __forceinline__ float2 cadd2(float2 a,float2 b){return make_float2(a.x+b.x,a.y+b.y);}
__device__ __forceinline__ float2 csub2(float2 a,float2 b){return make_float2(a.x-b.x,a.y-b.y);}
__device__ __forceinline__ int brev3i(int i){ return ((i&1)<<2)|(i&2)|((i>>2)&1); }

// ---------------- setup ----------------
__global__ void k_twid(){
  int k = threadIdx.x;
  double s,c; sincospi(-(double)k/32.0,&s,&c);
  g_tw[k] = make_float2((float)c,(float)s);
}

// all 3 gates in one launch: blockIdx.z = gate
__global__ void k_wtrans3(const float* __restrict__ zr, const float* __restrict__ zi,
                          const float* __restrict__ rr, const float* __restrict__ ri,
                          const float* __restrict__ hr, const float* __restrict__ hi){
  __shared__ float tr[32][33];
  __shared__ float ti[32][33];
  int gate = blockIdx.z;
  const float* wr = gate==0 ? zr : (gate==1 ? rr : hr);
  const float* wi = gate==0 ? zi : (gate==1 ? ri : hi);
  int m0 = blockIdx.x*32, io0 = blockIdx.y*32;
  int tx = threadIdx.x, ty = threadIdx.y;
  for (int r = ty; r < 32; r += 8){
    tr[r][tx] = wr[(size_t)(io0+r)*NMODE + m0 + tx];
    ti[r][tx] = wi[(size_t)(io0+r)*NMODE + m0 + tx];
  }
  __syncthreads();
  float2* dst = g_Wt[gate];
  for (int r = ty; r < 32; r += 8)
    dst[(size_t)(m0+r)*4096 + io0 + tx] = make_float2(tr[tx][r], ti[tx][r]);
}

// ---------------- 64-pt radix-8 FFT core ----------------
template<int SIGN>
__device__ __forceinline__ void fft8(float2 v[8]){
  const float C0 = 0.70710678118654752f;
  const float S = (float)SIGN;
  float2 t;
  t=v[1]; v[1]=csub2(v[0],t); v[0]=cadd2(v[0],t);
  t=v[3]; v[3]=csub2(v[2],t); v[2]=cadd2(v[2],t);
  t=v[5]; v[5]=csub2(v[4],t); v[4]=cadd2(v[4],t);
  t=v[7]; v[7]=csub2(v[6],t); v[6]=cadd2(v[6],t);
  t=v[2]; v[2]=csub2(v[0],t); v[0]=cadd2(v[0],t);
  t=make_float2(-S*v[3].y, S*v[3].x); v[3]=csub2(v[1],t); v[1]=cadd2(v[1],t);
  t=v[6]; v[6]=csub2(v[4],t); v[4]=cadd2(v[4],t);
  t=make_float2(-S*v[7].y, S*v[7].x); v[7]=csub2(v[5],t); v[5]=cadd2(v[5],t);
  t=v[4]; v[4]=csub2(v[0],t); v[0]=cadd2(v[0],t);
  t=make_float2(C0*(v[5].x - S*v[5].y), C0*(S*v[5].x + v[5].y));
  v[5]=csub2(v[1],t); v[1]=cadd2(v[1],t);
  t=make_float2(-S*v[6].y, S*v[6].x); v[6]=csub2(v[2],t); v[2]=cadd2(v[2],t);
  t=make_float2(-C0*(v[7].x + S*v[7].y), C0*(S*v[7].x - v[7].y));
  v[7]=csub2(v[3],t); v[3]=cadd2(v[3],t);
}

template<int SIGN>
__device__ void fft64_pass(float2* buf, const float2* stw, int tid, int xdim){
  int rs = xdim ? 65 : 1;
  int cs = xdim ? 1 : 65;
  #pragma unroll
  for (int q = 0; q < 2; q++){
    int slot = q*256 + tid;
    int line = slot & 63, j = slot >> 6;
    float2 v[8];
    #pragma unroll
    for (int i = 0; i < 8; i++) v[i] = buf[line*cs + (8*brev3i(i)+j)*rs];
    fft8<SIGN>(v);
    #pragma unroll
    for (int k1 = 1; k1 < 8; k1++){
      float2 w = stw[(k1*j) & 63];
      float wy = (SIGN < 0) ? w.y : -w.y;
      float2 a = v[k1];
      v[k1] = make_float2(a.x*w.x - a.y*wy, a.x*wy + a.y*w.x);
    }
    #pragma unroll
    for (int k1 = 0; k1 < 8; k1++) buf[line*cs + (k1*8+j)*rs] = v[k1];
  }
  __syncthreads();
  float2 vv[2][8];
  #pragma unroll
  for (int q = 0; q < 2; q++){
    int slot = q*256 + tid;
    int line = slot & 63, k1 = slot >> 6;
    #pragma unroll
    for (int i = 0; i < 8; i++) vv[q][i] = buf[line*cs + (k1*8 + brev3i(i))*rs];
    fft8<SIGN>(vv[q]);
  }
  __syncthreads();
  #pragma unroll
  for (int q = 0; q < 2; q++){
    int slot = q*256 + tid;
    int line = slot & 63, k1 = slot >> 6;
    #pragma unroll
    for (int k2 = 0; k2 < 8; k2++) buf[line*cs + (k1 + 8*k2)*rs] = vv[q][k2];
  }
  __syncthreads();
}

__device__ void load_herm_inv(float2* buf, const float2* stw, const float2* s, int tid){
  for (int e = tid; e < NMODE; e += 256){
    int xx = e/33, yy = e - xx*33;
    buf[xx*65 + yy] = s[e];
  }
  __syncthreads();
  for (int e = tid; e < 64*31; e += 256){
    int xx = e/31, yy = 33 + (e - (e/31)*31);
    float2 v = buf[((64-xx)&63)*65 + (64-yy)];
    buf[xx*65 + yy] = make_float2(v.x, -v.y);
  }
  __syncthreads();
  fft64_pass<1>(buf, stw, tid, 0);
  fft64_pass<1>(buf, stw, tid, 1);
}

__device__ void fwd_store_hf(float2* buf, const float2* stw, int tid, int img){
  fft64_pass<-1>(buf, stw, tid, 0);
  fft64_pass<-1>(buf, stw, tid, 1);
  float2* d = g_hf + (size_t)img*NMODE;
  for (int e = tid; e < NMODE; e += 256){
    int xx = e/33, yy = e - xx*33;
    d[e] = buf[xx*65 + yy];
  }
}

// ---------------- fused step kernels ----------------
// h0 = x*Wi + bi, then forward FFT
__global__ __launch_bounds__(256) void k_inmap_fft(const float* __restrict__ xin,
    const float* __restrict__ Wi, const float* __restrict__ bi){
  __shared__ float2 buf[64*65];
  __shared__ float2 stw[64];
  int tid = threadIdx.x, img = blockIdx.x;
  if (tid < 64) stw[tid] = g_tw[tid];
  int b = img >> 6, w = img & 63;
  float wi = Wi[w], bv = bi[w];
  float* hp = g_h + (size_t)img*NPIX;
  const float* xp = xin + ((size_t)b << 12);
  for (int e = tid; e < NPIX; e += 256){
    float v = xp[e]*wi + bv;
    hp[e] = v;
    buf[(e>>6)*65 + (e&63)] = make_float2(v, 0.f);
  }
  __syncthreads();
  fwd_store_hf(buf, stw, tid, img);
}

// irfft2(zf)->sigmoid->g_z ; then irfft2(rf)->sigmoid->*h->rfft2->g_hf
__global__ __launch_bounds__(256) void k_step1(){
  __shared__ float2 buf[64*65];
  __shared__ float2 stw[64];
  int tid = threadIdx.x, img = blockIdx.x;
  if (tid < 64) stw[tid] = g_tw[tid];
  load_herm_inv(buf, stw, g_zf + (size_t)img*NMODE, tid);
  float* zd = g_z + (size_t)img*NPIX;
  for (int e = tid; e < NPIX; e += 256){
    float v = buf[(e>>6)*65 + (e&63)].x * (1.f/4096.f);
    zd[e] = 1.f/(1.f + expf(-v));
  }
  __syncthreads();
  load_herm_inv(buf, stw, g_rf + (size_t)img*NMODE, tid);
  const float* hp = g_h + (size_t)img*NPIX;
  for (int e = tid; e < NPIX; e += 256){
    int pos = (e>>6)*65 + (e&63);
    float v = buf[pos].x * (1.f/4096.f);
    float r = 1.f/(1.f + expf(-v));
    buf[pos] = make_float2(r*hp[e], 0.f);
  }
  __syncthreads();
  fwd_store_hf(buf, stw, tid, img);
}

// irfft2(nf)->tanh->GRU update of h -> g_h, then forward FFT of new h -> g_hf
__global__ __launch_bounds__(256) void k_step2(){
  __shared__ float2 buf[64*65];
  __shared__ float2 stw[64];
  int tid = threadIdx.x, img = blockIdx.x;
  if (tid < 64) stw[tid] = g_tw[tid];
  load_herm_inv(buf, stw, g_rf + (size_t)img*NMODE, tid);
  float* hp = g_h + (size_t)img*NPIX;
  const float* zp = g_z + (size_t)img*NPIX;
  for (int e = tid; e < NPIX; e += 256){
    int pos = (e>>6)*65 + (e&63);
    float v = buf[pos].x * (1.f/4096.f);
    float nh = tanhf(v);
    float z = zp[e], h = hp[e];
    float hn = h + z*(nh - h);
    hp[e] = hn;
    buf[pos] = make_float2(hn, 0.f);
  }
  __syncthreads();
  fwd_store_hf(buf, stw, tid, img);
}

// ---------------- spectral channel mix ----------------
// b-pair f32x2 packing: accr holds (cr_b, cr_b+1), acci holds (ci_b, ci_b+1).
// No per-h swap movs; -wi folded into a per-weight pack.
// CTA = 4 modes, 8 warps: warp w -> mode w>>1, out-channels (w&1)*32 + lane.
template<int NG>
__global__ __launch_bounds__(256,2) void k_mix(){
  extern __shared__ float smx[];
  float*  sh_hr  = smx;                       // [4][64][16]
  float*  sh_hi  = smx + 4096;                // [4][64][16]
  float2* sh_out = (float2*)(smx + 8192);     // [4][1024]
  int tid = threadIdx.x;
  int m0 = blockIdx.x * 4;
  #pragma unroll
  for (int it = 0; it < 4; it++){
    int img = tid + it*256;                   // img = b*64 + i
    int b = img >> 6, i = img & 63;
    const float4* p = (const float4*)(g_hf + (size_t)img*NMODE + m0);
    float4 v0 = p[0], v1 = p[1];
    sh_hr[0*1024 + i*16 + b] = v0.x; sh_hi[0*1024 + i*16 + b] = v0.y;
    sh_hr[1*1024 + i*16 + b] = v0.z; sh_hi[1*1024 + i*16 + b] = v0.w;
    sh_hr[2*1024 + i*16 + b] = v1.x; sh_hi[2*1024 + i*16 + b] = v1.y;
    sh_hr[3*1024 + i*16 + b] = v1.z; sh_hi[3*1024 + i*16 + b] = v1.w;
  }
  __syncthreads();
  int wid = tid >> 5, lane = tid & 31;
  int ml = wid >> 1;
  int o = lane + ((wid & 1) << 5);
  const float* hr = sh_hr + ml*1024;
  const float* hi = sh_hi + ml*1024;
  #pragma unroll
  for (int g = 0; g < NG; g++){
    const float2* Wm = g_Wt[NG==1 ? 2 : g] + (size_t)(m0+ml)*4096 + o;
    ull accr[8], acci[8];
    #pragma unroll
    for (int bp = 0; bp < 8; bp++){ accr[bp]=0ull; acci[bp]=0ull; }
    #pragma unroll 4
    for (int i = 0; i < 64; i++){
      float2 w = Wm[(size_t)i*64];
      ull wr2  = pack2(w.x,  w.x);
      ull wi2  = pack2(w.y,  w.y);
      ull nwi2 = pack2(-w.y, -w.y);
      const ull* hrp = (const ull*)(hr + i*16);
      const ull* hip = (const ull*)(hi + i*16);
      #pragma unroll
      for (int bp = 0; bp < 8; bp++){
        ull hv = hrp[bp], gv = hip[bp];
        accr[bp] = ffma2(wr2,  hv, accr[bp]);
        acci[bp] = ffma2(wi2,  hv, acci[bp]);
        accr[bp] = ffma2(nwi2, gv, accr[bp]);
        acci[bp] = ffma2(wr2,  gv, acci[bp]);
      }
    }
    // stage to smem [ml][img] for coalesced global writes
    #pragma unroll
    for (int bp = 0; bp < 8; bp++){
      float r0,r1,i0,i1;
      unpack2(accr[bp], r0, r1);
      unpack2(acci[bp], i0, i1);
      sh_out[ml*1024 + (2*bp  )*64 + o] = make_float2(r0, i0);
      sh_out[ml*1024 + (2*bp+1)*64 + o] = make_float2(r1, i1);
    }
    __syncthreads();
    float2* dst = (NG==2 && g==0) ? g_zf : g_rf;
    #pragma unroll
    for (int it = 0; it < 4; it++){
      int img = tid + it*256;
      float2 a = sh_out[0*1024+img], b2 = sh_out[1*1024+img];
      float2 c = sh_out[2*1024+img], d  = sh_out[3*1024+img];
      float4* q = (float4*)(dst + (size_t)img*NMODE + m0);
      q[0] = make_float4(a.x, a.y, b2.x, b2.y);
      q[1] = make_float4(c.x, c.y, d.x,  d.y);
    }
    __syncthreads();
  }
}

// y[b][t][x][y] = sum_w h[b][w][x][y]*Wo[w] + bo
__global__ __launch_bounds__(256) void k_out(float* __restrict__ out,
    const float* __restrict__ Wo, const float* __restrict__ bo, int t){
  int idx = blockIdx.x*256 + threadIdx.x;
  int b = idx >> 12, xy = idx & 4095;
  float s = bo[0];
  const float* hp = g_h + (size_t)(b<<6)*NPIX + xy;
  #pragma unroll 8
  for (int w = 0; w < 64; w++) s += hp[(size_t)w*NPIX] * Wo[w];
  out[(size_t)((b*TSTEPS + t) << 12) + xy] = s;
}

// ---------------- launch ----------------
#define MIX_SMEM (8192*4 + 4096*8)   // 32KB planes + 32KB staging = 65536

extern "C" void kernel_launch(void* const* d_in, const int* in_sizes, int n_in,
                              void* d_out, int out_size){
  const float* x   = (const float*)d_in[0];
  const float* Wi  = (const float*)d_in[2];
  const float* bi  = (const float*)d_in[3];
  const float* Wo  = (const float*)d_in[4];
  const float* bo  = (const float*)d_in[5];
  const float* Wzr = (const float*)d_in[6];
  const float* Wzi = (const float*)d_in[7];
  const float* Wrr = (const float*)d_in[8];
  const float* Wri = (const float*)d_in[9];
  const float* Whr = (const float*)d_in[10];
  const float* Whi = (const float*)d_in[11];
  float* out = (float*)d_out;

  cudaFuncSetAttribute(k_mix<2>, cudaFuncAttributeMaxDynamicSharedMemorySize, MIX_SMEM);
  cudaFuncSetAttribute(k_mix<1>, cudaFuncAttributeMaxDynamicSharedMemorySize, MIX_SMEM);

  k_twid<<<1,64>>>();
  k_wtrans3<<<dim3(66,128,3), dim3(32,8)>>>(Wzr,Wzi,Wrr,Wri,Whr,Whi);
  k_inmap_fft<<<NIMG,256>>>(x, Wi, bi);

  for (int t = 0; t < TSTEPS; t++){
    k_mix<2><<<NMODE/4,256,MIX_SMEM>>>();   // hf -> zf, rf
    k_step1<<<NIMG,256>>>();                // zf->z ; rf->r*h -> hf
    k_mix<1><<<NMODE/4,256,MIX_SMEM>>>();   // hf -> nf (in rf)
    k_step2<<<NIMG,256>>>();                // nf->tanh, GRU update, fwd FFT -> hf
    k_out<<<256,256>>>(out, Wo, bo, t);     // y_t
  }
}

// round 8
// speedup vs baseline: 1.0727x; 1.0727x over previous
#include <cuda_runtime.h>
#include <math.h>

#define NB 16
#define NW 64
#define NIMG 1024
#define NPIX 4096
#define NYH 33
#define NMODE 2112
#define TSTEPS 20
typedef unsigned long long ull;

// ---------------- device global scratch ----------------
// Spectra layout: [mode][img]  (img = b*64 + channel)
__device__ float  g_h [NIMG*NPIX];              // hidden state [b][w][x][y]
__device__ float  g_z [NIMG*NPIX];              // sigmoid(z)
__device__ float2 g_hf[(size_t)NMODE*NIMG];
__device__ float2 g_zf[(size_t)NMODE*NIMG];
__device__ float2 g_rf[(size_t)NMODE*NIMG];     // r-spec, then n-spec
__device__ float2 g_Wt[3][(size_t)NMODE*4096];  // [gate][mode][i*64+o]
__device__ float2 g_tw[64];                     // W64^k forward twiddles

// ---------------- helpers ----------------
__device__ __forceinline__ ull pack2(float x, float y){
  ull r; asm("mov.b64 %0,{%1,%2};":"=l"(r):"f"(x),"f"(y)); return r;
}
__device__ __forceinline__ void unpack2(ull v, float& x, float& y){
  asm("mov.b64 {%0,%1},%2;":"=f"(x),"=f"(y):"l"(v));
}
__device__ __forceinline__ ull ffma2(ull a, ull b, ull c){
  ull d; asm("fma.rn.f32x2 %0,%1,%2,%3;":"=l"(d):"l"(a),"l"(b),"l"(c)); return d;
}
__device__ __forceinline__ float2 cadd2(float2 a,float2 b){return make_float2(a.x+b.x,a.y+b.y);}
__device__ __forceinline__ float2 csub2(float2 a,float2 b){return make_float2(a.x-b.x,a.y-b.y);}
__device__ __forceinline__ int brev3i(int i){ return ((i&1)<<2)|(i&2)|((i>>2)&1); }

// ---------------- setup ----------------
__global__ void k_twid(){
  int k = threadIdx.x;
  double s,c; sincospi(-(double)k/32.0,&s,&c);
  g_tw[k] = make_float2((float)c,(float)s);
}

__global__ void k_wtrans3(const float* __restrict__ zr, const float* __restrict__ zi,
                          const float* __restrict__ rr, const float* __restrict__ ri,
                          const float* __restrict__ hr, const float* __restrict__ hi){
  __shared__ float tr[32][33];
  __shared__ float ti[32][33];
  int gate = blockIdx.z;
  const float* wr = gate==0 ? zr : (gate==1 ? rr : hr);
  const float* wi = gate==0 ? zi : (gate==1 ? ri : hi);
  int m0 = blockIdx.x*32, io0 = blockIdx.y*32;
  int tx = threadIdx.x, ty = threadIdx.y;
  for (int r = ty; r < 32; r += 8){
    tr[r][tx] = wr[(size_t)(io0+r)*NMODE + m0 + tx];
    ti[r][tx] = wi[(size_t)(io0+r)*NMODE + m0 + tx];
  }
  __syncthreads();
  float2* dst = g_Wt[gate];
  for (int r = ty; r < 32; r += 8)
    dst[(size_t)(m0+r)*4096 + io0 + tx] = make_float2(tr[tx][r], ti[tx][r]);
}

// ---------------- 64-pt radix-8 FFT core ----------------
template<int SIGN>
__device__ __forceinline__ void fft8(float2 v[8]){
  const float C0 = 0.70710678118654752f;
  const float S = (float)SIGN;
  float2 t;
  t=v[1]; v[1]=csub2(v[0],t); v[0]=cadd2(v[0],t);
  t=v[3]; v[3]=csub2(v[2],t); v[2]=cadd2(v[2],t);
  t=v[5]; v[5]=csub2(v[4],t); v[4]=cadd2(v[4],t);
  t=v[7]; v[7]=csub2(v[6],t); v[6]=cadd2(v[6],t);
  t=v[2]; v[2]=csub2(v[0],t); v[0]=cadd2(v[0],t);
  t=make_float2(-S*v[3].y, S*v[3].x); v[3]=csub2(v[1],t); v[1]=cadd2(v[1],t);
  t=v[6]; v[6]=csub2(v[4],t); v[4]=cadd2(v[4],t);
  t=make_float2(-S*v[7].y, S*v[7].x); v[7]=csub2(v[5],t); v[5]=cadd2(v[5],t);
  t=v[4]; v[4]=csub2(v[0],t); v[0]=cadd2(v[0],t);
  t=make_float2(C0*(v[5].x - S*v[5].y), C0*(S*v[5].x + v[5].y));
  v[5]=csub2(v[1],t); v[1]=cadd2(v[1],t);
  t=make_float2(-S*v[6].y, S*v[6].x); v[6]=csub2(v[2],t); v[2]=cadd2(v[2],t);
  t=make_float2(-C0*(v[7].x + S*v[7].y), C0*(S*v[7].x - v[7].y));
  v[7]=csub2(v[3],t); v[3]=cadd2(v[3],t);
}

template<int SIGN>
__device__ void fft64_pass(float2* buf, const float2* stw, int tid, int xdim){
  int rs = xdim ? 65 : 1;
  int cs = xdim ? 1 : 65;
  #pragma unroll
  for (int q = 0; q < 2; q++){
    int slot = q*256 + tid;
    int line = slot & 63, j = slot >> 6;
    float2 v[8];
    #pragma unroll
    for (int i = 0; i < 8; i++) v[i] = buf[line*cs + (8*brev3i(i)+j)*rs];
    fft8<SIGN>(v);
    #pragma unroll
    for (int k1 = 1; k1 < 8; k1++){
      float2 w = stw[(k1*j) & 63];
      float wy = (SIGN < 0) ? w.y : -w.y;
      float2 a = v[k1];
      v[k1] = make_float2(a.x*w.x - a.y*wy, a.x*wy + a.y*w.x);
    }
    #pragma unroll
    for (int k1 = 0; k1 < 8; k1++) buf[line*cs + (k1*8+j)*rs] = v[k1];
  }
  __syncthreads();
  float2 vv[2][8];
  #pragma unroll
  for (int q = 0; q < 2; q++){
    int slot = q*256 + tid;
    int line = slot & 63, k1 = slot >> 6;
    #pragma unroll
    for (int i = 0; i < 8; i++) vv[q][i] = buf[line*cs + (k1*8 + brev3i(i))*rs];
    fft8<SIGN>(vv[q]);
  }
  __syncthreads();
  #pragma unroll
  for (int q = 0; q < 2; q++){
    int slot = q*256 + tid;
    int line = slot & 63, k1 = slot >> 6;
    #pragma unroll
    for (int k2 = 0; k2 < 8; k2++) buf[line*cs + (k1 + 8*k2)*rs] = vv[q][k2];
  }
  __syncthreads();
}

// load spectrum (strided [mode][img] layout), Hermitian-extend, inverse 2D FFT
__device__ void load_herm_inv(float2* buf, const float2* stw, const float2* s, int tid){
  for (int e = tid; e < NMODE; e += 256){
    int xx = e/33, yy = e - xx*33;
    buf[xx*65 + yy] = s[(size_t)e*NIMG];
  }
  __syncthreads();
  for (int e = tid; e < 64*31; e += 256){
    int xx = e/31, yy = 33 + (e - (e/31)*31);
    float2 v = buf[((64-xx)&63)*65 + (64-yy)];
    buf[xx*65 + yy] = make_float2(v.x, -v.y);
  }
  __syncthreads();
  fft64_pass<1>(buf, stw, tid, 0);
  fft64_pass<1>(buf, stw, tid, 1);
}

__device__ void fwd_store_hf(float2* buf, const float2* stw, int tid, int img){
  fft64_pass<-1>(buf, stw, tid, 0);
  fft64_pass<-1>(buf, stw, tid, 1);
  float2* d = g_hf + img;
  for (int e = tid; e < NMODE; e += 256){
    int xx = e/33, yy = e - xx*33;
    d[(size_t)e*NIMG] = buf[xx*65 + yy];
  }
}

// ---------------- fused step kernels ----------------
__global__ __launch_bounds__(256) void k_inmap_fft(const float* __restrict__ xin,
    const float* __restrict__ Wi, const float* __restrict__ bi){
  __shared__ float2 buf[64*65];
  __shared__ float2 stw[64];
  int tid = threadIdx.x, img = blockIdx.x;
  if (tid < 64) stw[tid] = g_tw[tid];
  int b = img >> 6, w = img & 63;
  float wi = Wi[w], bv = bi[w];
  float* hp = g_h + (size_t)img*NPIX;
  const float* xp = xin + ((size_t)b << 12);
  for (int e = tid; e < NPIX; e += 256){
    float v = xp[e]*wi + bv;
    hp[e] = v;
    buf[(e>>6)*65 + (e&63)] = make_float2(v, 0.f);
  }
  __syncthreads();
  fwd_store_hf(buf, stw, tid, img);
}

// irfft2(zf)->sigmoid->g_z ; irfft2(rf)->sigmoid->*h->rfft2->g_hf
__global__ __launch_bounds__(256) void k_step1(){
  __shared__ float2 buf[64*65];
  __shared__ float2 stw[64];
  int tid = threadIdx.x, img = blockIdx.x;
  if (tid < 64) stw[tid] = g_tw[tid];
  load_herm_inv(buf, stw, g_zf + img, tid);
  float* zd = g_z + (size_t)img*NPIX;
  for (int e = tid; e < NPIX; e += 256){
    float v = buf[(e>>6)*65 + (e&63)].x * (1.f/4096.f);
    zd[e] = 1.f/(1.f + expf(-v));
  }
  __syncthreads();
  load_herm_inv(buf, stw, g_rf + img, tid);
  const float* hp = g_h + (size_t)img*NPIX;
  for (int e = tid; e < NPIX; e += 256){
    int pos = (e>>6)*65 + (e&63);
    float v = buf[pos].x * (1.f/4096.f);
    float r = 1.f/(1.f + expf(-v));
    buf[pos] = make_float2(r*hp[e], 0.f);
  }
  __syncthreads();
  fwd_store_hf(buf, stw, tid, img);
}

// irfft2(nf)->tanh->GRU update -> g_h, then forward FFT -> g_hf
__global__ __launch_bounds__(256) void k_step2(){
  __shared__ float2 buf[64*65];
  __shared__ float2 stw[64];
  int tid = threadIdx.x, img = blockIdx.x;
  if (tid < 64) stw[tid] = g_tw[tid];
  load_herm_inv(buf, stw, g_rf + img, tid);
  float* hp = g_h + (size_t)img*NPIX;
  const float* zp = g_z + (size_t)img*NPIX;
  for (int e = tid; e < NPIX; e += 256){
    int pos = (e>>6)*65 + (e&63);
    float v = buf[pos].x * (1.f/4096.f);
    float nh = tanhf(v);
    float z = zp[e], h = hp[e];
    float hn = h + z*(nh - h);
    hp[e] = hn;
    buf[pos] = make_float2(hn, 0.f);
  }
  __syncthreads();
  fwd_store_hf(buf, stw, tid, img);
}

// ---------------- spectral channel mix ----------------
// Spectra [mode][img]: loads and stores are fully coalesced; no output staging.
// CTA = 4 modes, 8 warps: warp w -> mode (w>>1), out-channels (w&1)*32 + lane.
// h planes transposed in smem: [ml][i*18 + b] (stride 18 -> 8B-aligned b-pairs).
#define PL 1152   // 64*18 floats per mode plane

template<int NG>
__global__ __launch_bounds__(256,3) void k_mix(){
  extern __shared__ float smx[];
  float* sh_hr = smx;             // [4][PL]
  float* sh_hi = smx + 4*PL;      // [4][PL]
  int tid = threadIdx.x;
  int m0 = blockIdx.x * 4;
  // cooperative load: 4 contiguous mode rows of g_hf, transpose to [i][b]
  #pragma unroll
  for (int ml = 0; ml < 4; ml++){
    const float4* p = (const float4*)(g_hf + (size_t)(m0+ml)*NIMG);
    #pragma unroll
    for (int it = 0; it < 2; it++){
      int e = tid + it*256;              // covers img 2e, 2e+1
      float4 v = p[e];
      int img0 = 2*e;
      int b0 = img0>>6, i0 = img0&63;
      int b1 = (img0+1)>>6, i1 = (img0+1)&63;
      sh_hr[ml*PL + i0*18 + b0] = v.x; sh_hi[ml*PL + i0*18 + b0] = v.y;
      sh_hr[ml*PL + i1*18 + b1] = v.z; sh_hi[ml*PL + i1*18 + b1] = v.w;
    }
  }
  __syncthreads();
  int wid = tid >> 5, lane = tid & 31;
  int ml = wid >> 1;
  int o = lane + ((wid & 1) << 5);
  const float* hr = sh_hr + ml*PL;
  const float* hi = sh_hi + ml*PL;
  #pragma unroll
  for (int g = 0; g < NG; g++){
    const float2* Wm = g_Wt[NG==1 ? 2 : g] + (size_t)(m0+ml)*4096 + o;
    float2* dst = ((NG==2 && g==0) ? g_zf : g_rf) + (size_t)(m0+ml)*NIMG + o;
    ull accr[8], acci[8];
    #pragma unroll
    for (int bp = 0; bp < 8; bp++){ accr[bp]=0ull; acci[bp]=0ull; }
    #pragma unroll 1
    for (int blk = 0; blk < 8; blk++){
      float2 wv[8];
      #pragma unroll
      for (int u = 0; u < 8; u++) wv[u] = Wm[(size_t)(blk*8+u)*64];
      #pragma unroll
      for (int u = 0; u < 8; u++){
        int i = blk*8 + u;
        ull wr2  = pack2(wv[u].x,  wv[u].x);
        ull wi2  = pack2(wv[u].y,  wv[u].y);
        ull nwi2 = pack2(-wv[u].y, -wv[u].y);
        const ull* hrp = (const ull*)(hr + i*18);
        const ull* hip = (const ull*)(hi + i*18);
        #pragma unroll
        for (int bp = 0; bp < 8; bp++){
          ull hv = hrp[bp], gv = hip[bp];
          accr[bp] = ffma2(wr2,  hv, accr[bp]);
          acci[bp] = ffma2(wi2,  hv, acci[bp]);
          accr[bp] = ffma2(nwi2, gv, accr[bp]);
          acci[bp] = ffma2(wr2,  gv, acci[bp]);
        }
      }
    }
    // coalesced stores: lanes span consecutive images
    #pragma unroll
    for (int bp = 0; bp < 8; bp++){
      float r0,r1,i0,i1;
      unpack2(accr[bp], r0, r1);
      unpack2(acci[bp], i0, i1);
      dst[(size_t)(2*bp  )*64] = make_float2(r0, i0);
      dst[(size_t)(2*bp+1)*64] = make_float2(r1, i1);
    }
  }
}

// y[b][t][x][y] = sum_w h[b][w][x][y]*Wo[w] + bo
__global__ __launch_bounds__(256) void k_out(float* __restrict__ out,
    const float* __restrict__ Wo, const float* __restrict__ bo, int t){
  int idx = blockIdx.x*256 + threadIdx.x;
  int b = idx >> 12, xy = idx & 4095;
  float s = bo[0];
  const float* hp = g_h + (size_t)(b<<6)*NPIX + xy;
  #pragma unroll 8
  for (int w = 0; w < 64; w++) s += hp[(size_t)w*NPIX] * Wo[w];
  out[(size_t)((b*TSTEPS + t) << 12) + xy] = s;
}

// ---------------- launch ----------------
#define MIX_SMEM (8*PL*sizeof(float))   // 36864 B

extern "C" void kernel_launch(void* const* d_in, const int* in_sizes, int n_in,
                              void* d_out, int out_size){
  const float* x   = (const float*)d_in[0];
  const float* Wi  = (const float*)d_in[2];
  const float* bi  = (const float*)d_in[3];
  const float* Wo  = (const float*)d_in[4];
  const float* bo  = (const float*)d_in[5];
  const float* Wzr = (const float*)d_in[6];
  const float* Wzi = (const float*)d_in[7];
  const float* Wrr = (const float*)d_in[8];
  const float* Wri = (const float*)d_in[9];
  const float* Whr = (const float*)d_in[10];
  const float* Whi = (const float*)d_in[11];
  float* out = (float*)d_out;

  k_twid<<<1,64>>>();
  k_wtrans3<<<dim3(66,128,3), dim3(32,8)>>>(Wzr,Wzi,Wrr,Wri,Whr,Whi);
  k_inmap_fft<<<NIMG,256>>>(x, Wi, bi);

  for (int t = 0; t < TSTEPS; t++){
    k_mix<2><<<NMODE/4,256,MIX_SMEM>>>();   // hf -> zf, rf
    k_step1<<<NIMG,256>>>();                // zf->z ; rf->r*h -> hf
    k_mix<1><<<NMODE/4,256,MIX_SMEM>>>();   // hf -> nf (in rf)
    k_step2<<<NIMG,256>>>();                // nf->tanh, GRU update, fwd FFT -> hf
    k_out<<<256,256>>>(out, Wo, bo, t);     // y_t
  }
}

// round 13
// speedup vs baseline: 1.4953x; 1.3939x over previous
#include <cuda_runtime.h>
#include <math.h>

#define NB 16
#define NW 64
#define NIMG 1024
#define NPIX 4096
#define NYH 33
#define NMODE 2112
#define TSTEPS 20
typedef unsigned long long ull;

// ---------------- device global scratch ----------------
// Spectra layout: [mode][img]  (img = b*64 + channel)
__device__ float  g_h [NIMG*NPIX];
__device__ float  g_z [NIMG*NPIX];
__device__ __align__(16) float2 g_hf[(size_t)NMODE*NIMG];
__device__ __align__(16) float2 g_zf[(size_t)NMODE*NIMG];
__device__ __align__(16) float2 g_rf[(size_t)NMODE*NIMG];
__device__ float2 g_Wt[3][(size_t)NMODE*4096];  // [gate][mode][i*64+o]
__device__ float2 g_tw[64];

// ---------------- helpers ----------------
__device__ __forceinline__ ull pack2(float x, float y){
  ull r; asm("mov.b64 %0,{%1,%2};":"=l"(r):"f"(x),"f"(y)); return r;
}
__device__ __forceinline__ void unpack2(ull v, float& x, float& y){
  asm("mov.b64 {%0,%1},%2;":"=f"(x),"=f"(y):"l"(v));
}
__device__ __forceinline__ ull ffma2(ull a, ull b, ull c){
  ull d; asm("fma.rn.f32x2 %0,%1,%2,%3;":"=l"(d):"l"(a),"l"(b),"l"(c)); return d;
}
__device__ __forceinline__ float2 cadd2(float2 a,float2 b){return make_float2(a.x+b.x,a.y+b.y);}
__device__ __forceinline__ float2 csub2(float2 a,float2 b){return make_float2(a.x-b.x,a.y-b.y);}
__device__ __forceinline__ int brev3i(int i){ return ((i&1)<<2)|(i&2)|((i>>2)&1); }

// ---------------- setup ----------------
__global__ void k_twid(){
  int k = threadIdx.x;
  double s,c; sincospi(-(double)k/32.0,&s,&c);
  g_tw[k] = make_float2((float)c,(float)s);
}

__global__ void k_wtrans3(const float* __restrict__ zr, const float* __restrict__ zi,
                          const float* __restrict__ rr, const float* __restrict__ ri,
                          const float* __restrict__ hr, const float* __restrict__ hi){
  __shared__ float tr[32][33];
  __shared__ float ti[32][33];
  int gate = blockIdx.z;
  const float* wr = gate==0 ? zr : (gate==1 ? rr : hr);
  const float* wi = gate==0 ? zi : (gate==1 ? ri : hi);
  int m0 = blockIdx.x*32, io0 = blockIdx.y*32;
  int tx = threadIdx.x, ty = threadIdx.y;
  for (int r = ty; r < 32; r += 8){
    tr[r][tx] = wr[(size_t)(io0+r)*NMODE + m0 + tx];
    ti[r][tx] = wi[(size_t)(io0+r)*NMODE + m0 + tx];
  }
  __syncthreads();
  float2* dst = g_Wt[gate];
  for (int r = ty; r < 32; r += 8)
    dst[(size_t)(m0+r)*4096 + io0 + tx] = make_float2(tr[tx][r], ti[tx][r]);
}

// ---------------- 64-pt radix-8 FFT core ----------------
template<int SIGN>
__device__ __forceinline__ void fft8(float2 v[8]){
  const float C0 = 0.70710678118654752f;
  const float S = (float)SIGN;
  float2 t;
  t=v[1]; v[1]=csub2(v[0],t); v[0]=cadd2(v[0],t);
  t=v[3]; v[3]=csub2(v[2],t); v[2]=cadd2(v[2],t);
  t=v[5]; v[5]=csub2(v[4],t); v[4]=cadd2(v[4],t);
  t=v[7]; v[7]=csub2(v[6],t); v[6]=cadd2(v[6],t);
  t=v[2]; v[2]=csub2(v[0],t); v[0]=cadd2(v[0],t);
  t=make_float2(-S*v[3].y, S*v[3].x); v[3]=csub2(v[1],t); v[1]=cadd2(v[1],t);
  t=v[6]; v[6]=csub2(v[4],t); v[4]=cadd2(v[4],t);
  t=make_float2(-S*v[7].y, S*v[7].x); v[7]=csub2(v[5],t); v[5]=cadd2(v[5],t);
  t=v[4]; v[4]=csub2(v[0],t); v[0]=cadd2(v[0],t);
  t=make_float2(C0*(v[5].x - S*v[5].y), C0*(S*v[5].x + v[5].y));
  v[5]=csub2(v[1],t); v[1]=cadd2(v[1],t);
  t=make_float2(-S*v[6].y, S*v[6].x); v[6]=csub2(v[2],t); v[2]=cadd2(v[2],t);
  t=make_float2(-C0*(v[7].x + S*v[7].y), C0*(S*v[7].x - v[7].y));
  v[7]=csub2(v[3],t); v[3]=cadd2(v[3],t);
}

template<int SIGN>
__device__ void fft64_pass(float2* buf, const float2* stw, int tid, int xdim){
  int rs = xdim ? 65 : 1;
  int cs = xdim ? 1 : 65;
  #pragma unroll
  for (int q = 0; q < 2; q++){
    int slot = q*256 + tid;
    int line = slot & 63, j = slot >> 6;
    float2 v[8];
    #pragma unroll
    for (int i = 0; i < 8; i++) v[i] = buf[line*cs + (8*brev3i(i)+j)*rs];
    fft8<SIGN>(v);
    #pragma unroll
    for (int k1 = 1; k1 < 8; k1++){
      float2 w = stw[(k1*j) & 63];
      float wy = (SIGN < 0) ? w.y : -w.y;
      float2 a = v[k1];
      v[k1] = make_float2(a.x*w.x - a.y*wy, a.x*wy + a.y*w.x);
    }
    #pragma unroll
    for (int k1 = 0; k1 < 8; k1++) buf[line*cs + (k1*8+j)*rs] = v[k1];
  }
  __syncthreads();
  float2 vv[2][8];
  #pragma unroll
  for (int q = 0; q < 2; q++){
    int slot = q*256 + tid;
    int line = slot & 63, k1 = slot >> 6;
    #pragma unroll
    for (int i = 0; i < 8; i++) vv[q][i] = buf[line*cs + (k1*8 + brev3i(i))*rs];
    fft8<SIGN>(vv[q]);
  }
  __syncthreads();
  #pragma unroll
  for (int q = 0; q < 2; q++){
    int slot = q*256 + tid;
    int line = slot & 63, k1 = slot >> 6;
    #pragma unroll
    for (int k2 = 0; k2 < 8; k2++) buf[line*cs + (k1 + 8*k2)*rs] = vv[q][k2];
  }
  __syncthreads();
}

// ---- pair (2-for-1) spectrum load: build Z1ext + i*Z2ext, inverse 2D FFT ----
// src = spectra base + img0 (img0 even). Self-conjugate columns y=0,32 are
// x-symmetrized to match jnp irfft2 semantics for non-Hermitian input.
__device__ void load_pair_inv(float2* buf, const float2* stw, const float2* s, int tid){
  for (int e = tid; e < NMODE; e += 256){
    int xx = e/33, yy = e - xx*33;
    float4 v = *(const float4*)(s + (size_t)e*NIMG);
    if (yy == 0 || yy == 32){
      int mx = (64-xx)&63;
      float4 u = *(const float4*)(s + (size_t)(mx*33+yy)*NIMG);
      float z1x = 0.5f*(v.x+u.x), z1y = 0.5f*(v.y-u.y);
      float z2x = 0.5f*(v.z+u.z), z2y = 0.5f*(v.w-u.w);
      buf[xx*65+yy] = make_float2(z1x - z2y, z1y + z2x);
    } else {
      buf[xx*65+yy] = make_float2(v.x - v.w, v.y + v.z);
      buf[((64-xx)&63)*65 + (64-yy)] = make_float2(v.x + v.w, v.z - v.y);
    }
  }
  __syncthreads();
  fft64_pass<1>(buf, stw, tid, 0);
  fft64_pass<1>(buf, stw, tid, 1);
}

// ---- forward FFT of packed pair, unpack H1/H2, store to g_hf cols img0,img0+1 ----
__device__ void fwd_store_pair(float2* buf, const float2* stw, int tid, int img0){
  fft64_pass<-1>(buf, stw, tid, 0);
  fft64_pass<-1>(buf, stw, tid, 1);
  for (int e = tid; e < NMODE; e += 256){
    int xx = e/33, yy = e - xx*33;
    float2 F  = buf[xx*65 + yy];
    float2 Fm = buf[((64-xx)&63)*65 + ((64-yy)&63)];
    float4 o;
    o.x = 0.5f*(F.x + Fm.x); o.y = 0.5f*(F.y - Fm.y);   // H1
    o.z = 0.5f*(F.y + Fm.y); o.w = 0.5f*(Fm.x - F.x);   // H2
    *(float4*)(g_hf + (size_t)e*NIMG + img0) = o;
  }
}

// ---------------- fused step kernels (one CTA = channel pair) ----------------
__global__ __launch_bounds__(256) void k_inmap_fft(const float* __restrict__ xin,
    const float* __restrict__ Wi, const float* __restrict__ bi){
  __shared__ float2 buf[64*65];
  __shared__ float2 stw[64];
  int tid = threadIdx.x, img0 = blockIdx.x*2;
  if (tid < 64) stw[tid] = g_tw[tid];
  int b = img0 >> 6, w0 = img0 & 63;
  float wA = Wi[w0], wB = Wi[w0+1], bA = bi[w0], bB = bi[w0+1];
  float* hp = g_h + (size_t)img0*NPIX;
  const float* xp = xin + ((size_t)b << 12);
  for (int e = tid; e < NPIX; e += 256){
    float xv = xp[e];
    float v1 = xv*wA + bA, v2 = xv*wB + bB;
    hp[e] = v1; hp[NPIX+e] = v2;
    buf[(e>>6)*65 + (e&63)] = make_float2(v1, v2);
  }
  __syncthreads();
  fwd_store_pair(buf, stw, tid, img0);
}

// irfft2(zf pair)->sigmoid->g_z ; irfft2(rf pair)->sigmoid->*h->rfft2->g_hf
__global__ __launch_bounds__(256) void k_step1(){
  __shared__ float2 buf[64*65];
  __shared__ float2 stw[64];
  int tid = threadIdx.x, img0 = blockIdx.x*2;
  if (tid < 64) stw[tid] = g_tw[tid];
  load_pair_inv(buf, stw, g_zf + img0, tid);
  float* zd = g_z + (size_t)img0*NPIX;
  for (int e = tid; e < NPIX; e += 256){
    float2 v = buf[(e>>6)*65 + (e&63)];
    zd[e]      = 1.f/(1.f + expf(-v.x*(1.f/4096.f)));
    zd[NPIX+e] = 1.f/(1.f + expf(-v.y*(1.f/4096.f)));
  }
  __syncthreads();
  load_pair_inv(buf, stw, g_rf + img0, tid);
  const float* hp = g_h + (size_t)img0*NPIX;
  for (int e = tid; e < NPIX; e += 256){
    int pos = (e>>6)*65 + (e&63);
    float2 v = buf[pos];
    float r1 = 1.f/(1.f + expf(-v.x*(1.f/4096.f)));
    float r2 = 1.f/(1.f + expf(-v.y*(1.f/4096.f)));
    buf[pos] = make_float2(r1*hp[e], r2*hp[NPIX+e]);
  }
  __syncthreads();
  fwd_store_pair(buf, stw, tid, img0);
}

// irfft2(nf pair)->tanh->GRU update -> g_h, then forward FFT -> g_hf
__global__ __launch_bounds__(256) void k_step2(){
  __shared__ float2 buf[64*65];
  __shared__ float2 stw[64];
  int tid = threadIdx.x, img0 = blockIdx.x*2;
  if (tid < 64) stw[tid] = g_tw[tid];
  load_pair_inv(buf, stw, g_rf + img0, tid);
  float* hp = g_h + (size_t)img0*NPIX;
  const float* zp = g_z + (size_t)img0*NPIX;
  for (int e = tid; e < NPIX; e += 256){
    int pos = (e>>6)*65 + (e&63);
    float2 v = buf[pos];
    float nh1 = tanhf(v.x*(1.f/4096.f));
    float nh2 = tanhf(v.y*(1.f/4096.f));
    float z1 = zp[e],      h1 = hp[e];
    float z2 = zp[NPIX+e], h2 = hp[NPIX+e];
    float hn1 = h1 + z1*(nh1 - h1);
    float hn2 = h2 + z2*(nh2 - h2);
    hp[e] = hn1; hp[NPIX+e] = hn2;
    buf[pos] = make_float2(hn1, hn2);
  }
  __syncthreads();
  fwd_store_pair(buf, stw, tid, img0);
}

// ---------------- spectral channel mix ----------------
// NG=2: 8 warps = 2 modes x 2 o-halves x 2 gates, grid NMODE/2.
// NG=1: 8 warps = 4 modes x 2 o-halves (gate 2),  grid NMODE/4.
// h planes in smem at stride 20 floats (16B-aligned rows -> LDS.128 b-pairs).
template<int NG>
__global__ __launch_bounds__(256,3) void k_mix(){
  constexpr int NM = (NG==2) ? 2 : 4;
  extern __shared__ float smx[];   // [NM][2][64*20]
  int tid = threadIdx.x;
  int m0 = blockIdx.x * NM;
  #pragma unroll
  for (int ml = 0; ml < NM; ml++){
    const float4* p = (const float4*)(g_hf + (size_t)(m0+ml)*NIMG);
    float* hr = smx + (2*ml)*1280;
    float* hi = smx + (2*ml+1)*1280;
    #pragma unroll
    for (int it = 0; it < 2; it++){
      int e = tid + it*256;
      float4 v = p[e];
      int i0 = (2*e) & 63, b = (2*e) >> 6;
      hr[i0*20 + b] = v.x;     hi[i0*20 + b] = v.y;
      hr[(i0+1)*20 + b] = v.z; hi[(i0+1)*20 + b] = v.w;
    }
  }
  __syncthreads();
  int wid = tid >> 5, lane = tid & 31;
  int ml, half, gate;
  if (NG == 2){ ml = wid >> 2; half = (wid >> 1) & 1; gate = wid & 1; }
  else        { ml = wid >> 1; half = wid & 1;        gate = 2; }
  int o = lane + (half << 5);
  const float* hr = smx + (2*ml)*1280;
  const float* hi = smx + (2*ml+1)*1280;
  const float2* Wm = g_Wt[gate] + (size_t)(m0+ml)*4096 + o;
  float2* dst = (gate==0 ? g_zf : g_rf) + (size_t)(m0+ml)*NIMG + o;
  ull accr[8], acci[8];
  #pragma unroll
  for (int bp = 0; bp < 8; bp++){ accr[bp]=0ull; acci[bp]=0ull; }
  #pragma unroll 1
  for (int blk = 0; blk < 16; blk++){
    float2 wv[4];
    #pragma unroll
    for (int u = 0; u < 4; u++) wv[u] = Wm[(size_t)(blk*4+u)*64];
    #pragma unroll
    for (int u = 0; u < 4; u++){
      int i = blk*4 + u;
      ull wr2  = pack2(wv[u].x,  wv[u].x);
      ull wi2  = pack2(wv[u].y,  wv[u].y);
      ull nwi2 = pack2(-wv[u].y, -wv[u].y);
      const ulonglong2* hr2 = (const ulonglong2*)(hr + i*20);
      const ulonglong2* hi2 = (const ulonglong2*)(hi + i*20);
      #pragma unroll
      for (int c = 0; c < 4; c++){
        ulonglong2 hv = hr2[c], gv = hi2[c];
        accr[2*c]   = ffma2(wr2,  hv.x, accr[2*c]);
        acci[2*c]   = ffma2(wi2,  hv.x, acci[2*c]);
        accr[2*c]   = ffma2(nwi2, gv.x, accr[2*c]);
        acci[2*c]   = ffma2(wr2,  gv.x, acci[2*c]);
        accr[2*c+1] = ffma2(wr2,  hv.y, accr[2*c+1]);
        acci[2*c+1] = ffma2(wi2,  hv.y, acci[2*c+1]);
        accr[2*c+1] = ffma2(nwi2, gv.y, accr[2*c+1]);
        acci[2*c+1] = ffma2(wr2,  gv.y, acci[2*c+1]);
      }
    }
  }
  #pragma unroll
  for (int bp = 0; bp < 8; bp++){
    float r0,r1,i0,i1;
    unpack2(accr[bp], r0, r1);
    unpack2(acci[bp], i0, i1);
    dst[(size_t)(2*bp  )*64] = make_float2(r0, i0);
    dst[(size_t)(2*bp+1)*64] = make_float2(r1, i1);
  }
}

// y[b][t][x][y] = sum_w h[b][w][x][y]*Wo[w] + bo
__global__ __launch_bounds__(256) void k_out(float* __restrict__ out,
    const float* __restrict__ Wo, const float* __restrict__ bo, int t){
  int idx = blockIdx.x*256 + threadIdx.x;
  int b = idx >> 12, xy = idx & 4095;
  float s = bo[0];
  const float* hp = g_h + (size_t)(b<<6)*NPIX + xy;
  #pragma unroll 8
  for (int w = 0; w < 64; w++) s += hp[(size_t)w*NPIX] * Wo[w];
  out[(size_t)((b*TSTEPS + t) << 12) + xy] = s;
}

// ---------------- launch ----------------
#define MIX2_SMEM (2*2*1280*4)   // 20480 B
#define MIX1_SMEM (4*2*1280*4)   // 40960 B

extern "C" void kernel_launch(void* const* d_in, const int* in_sizes, int n_in,
                              void* d_out, int out_size){
  const float* x   = (const float*)d_in[0];
  const float* Wi  = (const float*)d_in[2];
  const float* bi  = (const float*)d_in[3];
  const float* Wo  = (const float*)d_in[4];
  const float* bo  = (const float*)d_in[5];
  const float* Wzr = (const float*)d_in[6];
  const float* Wzi = (const float*)d_in[7];
  const float* Wrr = (const float*)d_in[8];
  const float* Wri = (const float*)d_in[9];
  const float* Whr = (const float*)d_in[10];
  const float* Whi = (const float*)d_in[11];
  float* out = (float*)d_out;

  k_twid<<<1,64>>>();
  k_wtrans3<<<dim3(66,128,3), dim3(32,8)>>>(Wzr,Wzi,Wrr,Wri,Whr,Whi);
  k_inmap_fft<<<NIMG/2,256>>>(x, Wi, bi);

  for (int t = 0; t < TSTEPS; t++){
    k_mix<2><<<NMODE/2,256,MIX2_SMEM>>>();   // hf -> zf, rf
    k_step1<<<NIMG/2,256>>>();               // zf->z ; rf->r*h -> hf
    k_mix<1><<<NMODE/4,256,MIX1_SMEM>>>();   // hf -> nf (in rf)
    k_step2<<<NIMG/2,256>>>();               // nf->tanh, GRU update, fwd FFT -> hf
    k_out<<<256,256>>>(out, Wo, bo, t);      // y_t
  }
}